// round 17
// baseline (speedup 1.0000x reference)
#include <cuda_runtime.h>
#include <cuda_bf16.h>
#include <cstdint>

// NEAT DAG — R17: R12 skeleton + cp.async staging + 16x32 warp tiles +
// register-resident triangle.
// x[4096,512] f32, W[1536,2048] f32 lower-tri, b[1536], out[4096,256].
// 128 CTAs x 32 batch rows, 512 threads (16 warps -> 8 MMA warps in 2
// split-K groups; all 512 stage via cp.async).

#define NTH 512
#define BR 32
#define NIN 512
#define NN 2048
#define NCHUNK 24
#define ZST 66

__device__ __align__(256) __nv_bfloat16 g_Ahi[4096u * 2048u];
__device__ __align__(256) __nv_bfloat16 g_Alo[4096u * 2048u];
__device__ __align__(256) __nv_bfloat16 g_Whi[1536u * 2048u];
__device__ __align__(256) __nv_bfloat16 g_Wlo[1536u * 2048u];

// ---- smem layout (bytes) ----
#define OFF_BIAS 0
#define OFF_ZSM  256                    // 32*66*4 = 8448
#define OFF_WD   8960                   // 64*68*4 = 17408
#define OFF_BUFS 27648                  // 4 buffers (2 groups x 2 parity)
#define BUFSZ    24576                  // AHI 4K | ALO 4K | WHI 8K | WLO 8K
#define SMEM_SZ  (OFF_BUFS + 4 * BUFSZ) // 125952
#define AHI 0
#define ALO 4096
#define WHI 8192
#define WLO 16384

#define SW128(b) ((b) ^ (((b) >> 3) & 0x70))

__device__ __forceinline__ uint32_t smem_u32(const void* p) {
    uint32_t a;
    asm("{ .reg .u64 t; cvta.to.shared.u64 t, %1; cvt.u32.u64 %0, t; }" : "=r"(a) : "l"(p));
    return a;
}
__device__ __forceinline__ void cpa16(uint32_t dst, const void* src) {
    asm volatile("cp.async.cg.shared.global [%0], [%1], 16;"
                 :: "r"(dst), "l"(src) : "memory");
}
#define CPA_COMMIT() asm volatile("cp.async.commit_group;" ::: "memory")
#define CPA_WAIT0()  asm volatile("cp.async.wait_group 0;" ::: "memory")

__device__ __forceinline__ void ldm4(uint32_t* r, uint32_t addr) {
    asm volatile("ldmatrix.sync.aligned.m8n8.x4.shared.b16 {%0,%1,%2,%3}, [%4];"
                 : "=r"(r[0]), "=r"(r[1]), "=r"(r[2]), "=r"(r[3]) : "r"(addr));
}
__device__ __forceinline__ void mma_bf16(float* d, const uint32_t* a,
                                         uint32_t b0, uint32_t b1) {
    asm volatile(
        "mma.sync.aligned.m16n8k16.row.col.f32.bf16.bf16.f32 "
        "{%0,%1,%2,%3}, {%4,%5,%6,%7}, {%8,%9}, {%0,%1,%2,%3};"
        : "+f"(d[0]), "+f"(d[1]), "+f"(d[2]), "+f"(d[3])
        : "r"(a[0]), "r"(a[1]), "r"(a[2]), "r"(a[3]), "r"(b0), "r"(b1));
}
__device__ __forceinline__ void split4(float4 v, __nv_bfloat16* h, __nv_bfloat16* l) {
    float f[4] = {v.x, v.y, v.z, v.w};
    #pragma unroll
    for (int j = 0; j < 4; j++) {
        h[j] = __float2bfloat16(f[j]);
        l[j] = __float2bfloat16(f[j] - __bfloat162float(h[j]));
    }
}

#define XN4 (4096 * 512 / 4)
#define WN4 (1536 * 2048 / 4)
__global__ void conv_kernel(const float* __restrict__ x, const float* __restrict__ W) {
    int idx = blockIdx.x * blockDim.x + threadIdx.x;
    __align__(8) __nv_bfloat16 h[4], l[4];
    if (idx < XN4) {
        int r = idx >> 7, c = (idx & 127) * 4;
        split4(*(const float4*)&x[(size_t)r * NIN + c], h, l);
        size_t o = (size_t)r * NN + c;
        *(uint2*)&g_Ahi[o] = *(uint2*)h;
        *(uint2*)&g_Alo[o] = *(uint2*)l;
    } else if (idx < XN4 + WN4) {
        int j = idx - XN4;
        int r = j >> 9, c = (j & 511) * 4;
        size_t o = (size_t)r * NN + c;
        split4(*(const float4*)&W[o], h, l);
        *(uint2*)&g_Whi[o] = *(uint2*)h;
        *(uint2*)&g_Wlo[o] = *(uint2*)l;
    }
}

__global__ void __launch_bounds__(NTH, 1)
neat_mma_kernel(const float* __restrict__ W,
                const float* __restrict__ bias,
                float* __restrict__ out)
{
    extern __shared__ char sm[];
    const uint32_t sb = smem_u32(sm);
    const int tid = threadIdx.x;
    const int lane = tid & 31, wrp = tid >> 5;
    const int grp = wrp >> 2, sub = wrp & 3;   // grp 0/1 compute (wrp < 8)
    const int row0 = blockIdx.x * BR;

    float* biasS = (float*)(sm + OFF_BIAS);
    float* zSm   = (float*)(sm + OFF_ZSM);    // [32][66]
    float* Wd    = (float*)(sm + OFF_WD);     // [64][68] fp32 diag

    // MMA mapping: warp covers rows rt16..+16, cols c0..c0+32
    const int rt16 = (sub & 1) << 4;
    const int c0   = (sub >> 1) << 5;
    const int mrow = lane & 7, mid = lane >> 3;
    const int aRowB  = (rt16 + mrow + ((mid & 1) << 3)) * 128 + ((mid >> 1) << 4);
    const int wRowB0 = (c0 + mrow + ((mid >> 1) << 3)) * 128 + ((mid & 1) << 4);
    const int wRowB1 = wRowB0 + 16 * 128;

    // cp.async staging map: 3 items/thread/block
    //   item0: A (hi if tid<256 else lo), row=(tid&255)>>3, sg=tid&7
    //   item1: WHI row tid>>3 ... wait: W rows need 64 rows x 8 segs = 512
    const int arow = (tid & 255) >> 3, asg = tid & 7;
    const __nv_bfloat16* aSrc =
        (tid < 256 ? g_Ahi : g_Alo) + (size_t)(row0 + arow) * NN + 8 * asg;
    const uint32_t aDst = (tid < 256 ? AHI : ALO)
                        + SW128((uint32_t)(arow * 128 + asg * 16));
    const int wr = tid >> 3, wsg = tid & 7;
    const size_t wOff = (size_t)wr * NN + 8 * wsg;
    const uint32_t wDstH = WHI + SW128((uint32_t)(wr * 128 + wsg * 16));
    const uint32_t wDstL = WLO + SW128((uint32_t)(wr * 128 + wsg * 16));

    auto stage_pair = [&](int i0, int nblk, int it, int par) {
        #pragma unroll
        for (int g = 0; g < 2; g++) {
            int b = 2 * it + g;
            if (b < nblk) {
                int kb = 64 * b;
                uint32_t bd = sb + OFF_BUFS + (uint32_t)((g * 2 + par) * BUFSZ);
                cpa16(bd + aDst, aSrc + kb);
                size_t wo = (size_t)i0 * NN + kb + wOff;
                cpa16(bd + wDstH, g_Whi + wo);
                cpa16(bd + wDstL, g_Wlo + wo);
            }
        }
        CPA_COMMIT();
    };

    float d[4][4];

    for (int ch = 0; ch < NCHUNK; ch++) {
        const int i0 = ch * 64, g0 = NIN + i0;
        const int nblk = g0 >> 6;
        const int nit = (nblk + 1) >> 1;

        #pragma unroll
        for (int t = 0; t < 4; t++)
            #pragma unroll
            for (int e = 0; e < 4; e++) d[t][e] = 0.0f;

        stage_pair(i0, nblk, 0, 0);

        for (int it = 0; it < nit; it++) {
            const int par = it & 1;
            CPA_WAIT0();
            __syncthreads();
            if (it + 1 < nit) stage_pair(i0, nblk, it + 1, par ^ 1);
            if (wrp < 8 && (2 * it + grp) < nblk) {
                const uint32_t bb = sb + OFF_BUFS
                                  + (uint32_t)((grp * 2 + par) * BUFSZ);
                #pragma unroll
                for (int ks = 0; ks < 4; ks++) {
                    uint32_t koff = ks * 32;
                    uint32_t ah[4], al[4], wh0[4], wh1[4], wl0[4], wl1[4];
                    ldm4(ah,  bb + AHI + SW128((uint32_t)(aRowB  + koff)));
                    ldm4(al,  bb + ALO + SW128((uint32_t)(aRowB  + koff)));
                    ldm4(wh0, bb + WHI + SW128((uint32_t)(wRowB0 + koff)));
                    ldm4(wh1, bb + WHI + SW128((uint32_t)(wRowB1 + koff)));
                    ldm4(wl0, bb + WLO + SW128((uint32_t)(wRowB0 + koff)));
                    ldm4(wl1, bb + WLO + SW128((uint32_t)(wRowB1 + koff)));
                    mma_bf16(d[0], ah, wh0[0], wh0[1]);
                    mma_bf16(d[0], ah, wl0[0], wl0[1]);
                    mma_bf16(d[0], al, wh0[0], wh0[1]);
                    mma_bf16(d[1], ah, wh0[2], wh0[3]);
                    mma_bf16(d[1], ah, wl0[2], wl0[3]);
                    mma_bf16(d[1], al, wh0[2], wh0[3]);
                    mma_bf16(d[2], ah, wh1[0], wh1[1]);
                    mma_bf16(d[2], ah, wl1[0], wl1[1]);
                    mma_bf16(d[2], al, wh1[0], wh1[1]);
                    mma_bf16(d[3], ah, wh1[2], wh1[3]);
                    mma_bf16(d[3], ah, wl1[2], wl1[3]);
                    mma_bf16(d[3], al, wh1[2], wh1[3]);
                }
            }
        }

        // ---- stage fp32 diagonal block + bias ----
        #pragma unroll
        for (int i = 0; i < 2; i++) {
            int idx = tid + i * NTH;            // 0..1023
            int r = idx >> 4, q = idx & 15;
            *(float4*)&Wd[r * 68 + 4 * q] =
                *(const float4*)&W[(size_t)(i0 + r) * NN + g0 + 4 * q];
        }
        if (tid < 64) biasS[tid] = bias[i0 + tid];
        __syncthreads();

        // ---- merge group fragments into zSm (+bias) ----
        {
            int rw = rt16 + (lane >> 2);
            int cbb = 2 * (lane & 3);
            if (wrp < 4) {
                #pragma unroll
                for (int t = 0; t < 4; t++) {
                    int cb = c0 + 8 * t + cbb;
                    *(float2*)&zSm[rw * ZST + cb] =
                        make_float2(d[t][0] + biasS[cb], d[t][1] + biasS[cb + 1]);
                    *(float2*)&zSm[(rw + 8) * ZST + cb] =
                        make_float2(d[t][2] + biasS[cb], d[t][3] + biasS[cb + 1]);
                }
            }
            __syncthreads();
            if (wrp >= 4 && wrp < 8) {
                #pragma unroll
                for (int t = 0; t < 4; t++) {
                    int cb = c0 + 8 * t + cbb;
                    float2 a = *(float2*)&zSm[rw * ZST + cb];
                    a.x += d[t][0]; a.y += d[t][1];
                    *(float2*)&zSm[rw * ZST + cb] = a;
                    a = *(float2*)&zSm[(rw + 8) * ZST + cb];
                    a.x += d[t][2]; a.y += d[t][3];
                    *(float2*)&zSm[(rw + 8) * ZST + cb] = a;
                }
            }
            __syncthreads();
        }

        // ---- triangle: warp 0, one lane per batch row, register-resident ----
        if (wrp == 0) {
            const int row = lane;
            float z[64];
            #pragma unroll
            for (int j = 0; j < 64; j++) z[j] = zSm[row * ZST + j];
            #pragma unroll
            for (int j = 0; j < 64; j++) {
                float t5 = fminf(fmaxf(5.0f * z[j], -60.0f), 60.0f);
                float o  = __fdividef(1.0f, 1.0f + __expf(-t5));
                __nv_bfloat16 h = __float2bfloat16(o);
                size_t go = (size_t)(row0 + row) * NN + g0 + j;
                g_Ahi[go] = h;
                g_Alo[go] = __float2bfloat16(o - __bfloat162float(h));
                if (g0 + j >= NN - 256)
                    out[(size_t)(row0 + row) * 256 + (g0 + j - (NN - 256))] = o;
                #pragma unroll
                for (int k = j + 1; k < 64; k++)
                    z[k] = fmaf(Wd[k * 68 + j], o, z[k]);
            }
            __threadfence_block();
        }
        __syncthreads();   // triangle activations visible to next chunk staging
    }
}

extern "C" void kernel_launch(void* const* d_in, const int* in_sizes, int n_in,
                              void* d_out, int out_size) {
    const float* x    = (const float*)d_in[0];
    const float* W    = (const float*)d_in[1];
    const float* bias = (const float*)d_in[2];
    float* out        = (float*)d_out;
    (void)in_sizes; (void)n_in; (void)out_size;

    conv_kernel<<<(XN4 + WN4 + NTH - 1) / NTH, NTH>>>(x, W);
    cudaFuncSetAttribute(neat_mma_kernel,
                         cudaFuncAttributeMaxDynamicSharedMemorySize, SMEM_SZ);
    neat_mma_kernel<<<4096 / BR, NTH, SMEM_SZ>>>(W, bias, out);
}